// round 1
// baseline (speedup 1.0000x reference)
#include <cuda_runtime.h>
#include <cstdint>
#include <cstddef>

// Problem constants (fixed shapes for this problem instance)
#define EE 131072
#define TT 1048576
#define HH 128
#define NRBF 6
#define NSBF 42
#define NBIL 8

// ---------------------------------------------------------------------------
// Scratch (device globals; no runtime allocation allowed)
// ---------------------------------------------------------------------------
__device__ float g_rbfp[(size_t)EE * HH];          //  64 MB  rbf @ W_rbf
__device__ float g_g   [(size_t)EE * HH];          //  64 MB  silu(m@W_kj+b)*rbfp
__device__ float g_p   [(size_t)TT * NBIL];        //  32 MB  sbf @ W_sbf
__device__ float g_U   [(size_t)EE * NBIL * HH];   // 512 MB  g @ W_bil_flat
__device__ float g_m1  [(size_t)EE * HH];          //  64 MB  x_ji (+= aggr via atomics)
__device__ float g_tb  [(size_t)EE * HH];          //  64 MB  residual temp
__device__ float g_m2  [(size_t)EE * HH];          //  64 MB
__device__ float g_m3  [(size_t)EE * HH];          //  64 MB

__device__ __forceinline__ float silu_f(float x) {
    return x / (1.0f + __expf(-x));
}

// ---------------------------------------------------------------------------
// Generic fp32 GEMM: C[M,128-tile] = op(A[M,128]) @ W[128, ldw] + epilogue
// Block tile 128x128, 256 threads, 8x8 micro-tile, K=128 in 8 stages of 16.
// MODE: 0 = raw (no bias/act)
//       1 = silu(acc + bias)
//       2 = silu(acc + bias) * extra[row, n]
//       3 = acc + bias + extra[row, n]
//       4 = extra[row, n] + silu(acc + bias)
// PRE:  1 = apply silu to A elements on load.
// ---------------------------------------------------------------------------
template <int MODE, int PRE>
__global__ void __launch_bounds__(256)
gemm_k(const float* __restrict__ A,
       const float* __restrict__ W, int ldw,
       const float* __restrict__ bias,
       const float* __restrict__ extra,
       float* __restrict__ C, int ldc)
{
    __shared__ float As[16][132];   // [k][m], padded stride to spread banks
    __shared__ float Ws[16][128];   // [k][n]

    const int m0  = blockIdx.x * 128;
    const int n0  = blockIdx.y * 128;
    const int tid = threadIdx.x;

    const int tr   = tid >> 4;      // 0..15
    const int tc   = tid & 15;      // 0..15
    const int row0 = tr * 8;
    const int col0 = tc * 8;

    const int ar = tid >> 2;        // 0..63 (A-load row)
    const int ac = tid & 3;         // 0..3  (A-load k-chunk)
    const int kr = tid >> 5;        // 0..7  (W-load k row)
    const int cw = tid & 31;        // 0..31 (W-load col chunk)

    const float* Ag = A + (size_t)m0 * HH;
    const float* Wg = W + n0;

    float acc[8][8];
#pragma unroll
    for (int i = 0; i < 8; ++i)
#pragma unroll
        for (int j = 0; j < 8; ++j) acc[i][j] = 0.0f;

    for (int k0 = 0; k0 < HH; k0 += 16) {
        // Load A tile [128 rows x 16 k], transpose into As[k][m]
#pragma unroll
        for (int pss = 0; pss < 2; ++pss) {
            int r = ar + pss * 64;
            float4 v = *reinterpret_cast<const float4*>(Ag + (size_t)r * HH + k0 + ac * 4);
            if (PRE) {
                v.x = silu_f(v.x); v.y = silu_f(v.y);
                v.z = silu_f(v.z); v.w = silu_f(v.w);
            }
            As[ac * 4 + 0][r] = v.x;
            As[ac * 4 + 1][r] = v.y;
            As[ac * 4 + 2][r] = v.z;
            As[ac * 4 + 3][r] = v.w;
        }
        // Load W tile [16 k x 128 n]
#pragma unroll
        for (int pss = 0; pss < 2; ++pss) {
            int kk = kr + pss * 8;
            float4 v = *reinterpret_cast<const float4*>(Wg + (size_t)(k0 + kk) * ldw + cw * 4);
            *reinterpret_cast<float4*>(&Ws[kk][cw * 4]) = v;
        }
        __syncthreads();

#pragma unroll
        for (int kk = 0; kk < 16; ++kk) {
            float4 a0 = *reinterpret_cast<const float4*>(&As[kk][row0]);
            float4 a1 = *reinterpret_cast<const float4*>(&As[kk][row0 + 4]);
            float4 b0 = *reinterpret_cast<const float4*>(&Ws[kk][col0]);
            float4 b1 = *reinterpret_cast<const float4*>(&Ws[kk][col0 + 4]);
            float a[8], b[8];
            a[0] = a0.x; a[1] = a0.y; a[2] = a0.z; a[3] = a0.w;
            a[4] = a1.x; a[5] = a1.y; a[6] = a1.z; a[7] = a1.w;
            b[0] = b0.x; b[1] = b0.y; b[2] = b0.z; b[3] = b0.w;
            b[4] = b1.x; b[5] = b1.y; b[6] = b1.z; b[7] = b1.w;
#pragma unroll
            for (int i = 0; i < 8; ++i)
#pragma unroll
                for (int j = 0; j < 8; ++j)
                    acc[i][j] += a[i] * b[j];
        }
        __syncthreads();
    }

    // Epilogue
#pragma unroll
    for (int i = 0; i < 8; ++i) {
        size_t row = (size_t)(m0 + row0 + i);
#pragma unroll
        for (int jv = 0; jv < 2; ++jv) {
            int nc = col0 + jv * 4;
            float4 v = make_float4(acc[i][jv * 4 + 0], acc[i][jv * 4 + 1],
                                   acc[i][jv * 4 + 2], acc[i][jv * 4 + 3]);
            if (MODE != 0) {
                float4 bb = *reinterpret_cast<const float4*>(bias + n0 + nc);
                v.x += bb.x; v.y += bb.y; v.z += bb.z; v.w += bb.w;
            }
            if (MODE == 1 || MODE == 2 || MODE == 4) {
                v.x = silu_f(v.x); v.y = silu_f(v.y);
                v.z = silu_f(v.z); v.w = silu_f(v.w);
            }
            if (MODE == 2) {
                float4 mm = *reinterpret_cast<const float4*>(extra + row * HH + nc);
                v.x *= mm.x; v.y *= mm.y; v.z *= mm.z; v.w *= mm.w;
            }
            if (MODE == 3 || MODE == 4) {
                float4 rr = *reinterpret_cast<const float4*>(extra + row * HH + nc);
                v.x += rr.x; v.y += rr.y; v.z += rr.z; v.w += rr.w;
            }
            *reinterpret_cast<float4*>(C + row * (size_t)ldc + n0 + nc) = v;
        }
    }
}

// ---------------------------------------------------------------------------
// rbfproj[e, c] = sum_r rbf[e, r] * W_rbf[r, c]      (E*H threads)
// ---------------------------------------------------------------------------
__global__ void __launch_bounds__(256)
rbfproj_kernel(const float* __restrict__ rbf,
               const float* __restrict__ Wrbf,
               float* __restrict__ out)
{
    int idx = blockIdx.x * 256 + threadIdx.x;
    int e = idx >> 7;
    int c = idx & 127;
    const float* r = rbf + (size_t)e * NRBF;
    float acc = 0.0f;
#pragma unroll
    for (int k = 0; k < NRBF; ++k)
        acc += r[k] * Wrbf[k * HH + c];
    out[idx] = acc;
}

// ---------------------------------------------------------------------------
// p[t, b] = sum_k sbf[t, k] * W_sbf[k, b]     (32 triplets per block)
// ---------------------------------------------------------------------------
__global__ void __launch_bounds__(256)
sbfproj_kernel(const float* __restrict__ sbf,
               const float* __restrict__ Wsbf,
               float* __restrict__ p)
{
    __shared__ float s_sbf[32][NSBF];
    __shared__ float s_w[NSBF][NBIL];

    int t0  = blockIdx.x * 32;
    int tid = threadIdx.x;

    for (int i = tid; i < NSBF * NBIL; i += 256)
        s_w[i / NBIL][i % NBIL] = Wsbf[i];
    for (int i = tid; i < 32 * NSBF; i += 256) {
        int tl = i / NSBF, c = i % NSBF;
        s_sbf[tl][c] = sbf[(size_t)(t0 + tl) * NSBF + c];
    }
    __syncthreads();

    int tl = tid >> 3;   // 0..31
    int b  = tid & 7;    // 0..7
    float acc = 0.0f;
#pragma unroll
    for (int k = 0; k < NSBF; ++k)
        acc += s_sbf[tl][k] * s_w[k][b];
    p[(size_t)(t0 + tl) * NBIL + b] = acc;
}

// ---------------------------------------------------------------------------
// Triplet message + scatter: one warp per triplet.
//   msg[t, :] = sum_b p[t,b] * U[kj_t, b*128 : b*128+128]
//   atomicAdd into out[ji_t, :]   (out pre-loaded with x_ji)
// ---------------------------------------------------------------------------
__global__ void __launch_bounds__(256)
msg_kernel(const float* __restrict__ U,
           const int* __restrict__ kj,
           const int* __restrict__ ji,
           const float* __restrict__ p,
           float* __restrict__ out)
{
    int warp = (blockIdx.x * 256 + threadIdx.x) >> 5;
    int lane = threadIdx.x & 31;

    int ekj = kj[warp];
    int eji = ji[warp];

    const float4* u = reinterpret_cast<const float4*>(U + (size_t)ekj * (NBIL * HH)) + lane;
    const float* pp = p + (size_t)warp * NBIL;

    float pb[NBIL];
#pragma unroll
    for (int b = 0; b < NBIL; ++b) pb[b] = pp[b];

    float4 acc = make_float4(0.f, 0.f, 0.f, 0.f);
#pragma unroll
    for (int b = 0; b < NBIL; ++b) {
        float4 uv = u[b * 32];
        acc.x += pb[b] * uv.x;
        acc.y += pb[b] * uv.y;
        acc.z += pb[b] * uv.z;
        acc.w += pb[b] * uv.w;
    }

    float* o = out + (size_t)eji * HH + lane * 4;
    atomicAdd(o + 0, acc.x);
    atomicAdd(o + 1, acc.y);
    atomicAdd(o + 2, acc.z);
    atomicAdd(o + 3, acc.w);
}

// ---------------------------------------------------------------------------
// Launch
// ---------------------------------------------------------------------------
extern "C" void kernel_launch(void* const* d_in, const int* in_sizes, int n_in,
                              void* d_out, int out_size)
{
    const float* m     = (const float*)d_in[0];
    const float* rbf   = (const float*)d_in[1];
    const float* sbf   = (const float*)d_in[2];
    // d_in[3] = edge_index (unused by the reference)
    const int*   tri   = (const int*)d_in[4];
    const float* W_rbf = (const float*)d_in[5];
    const float* W_sbf = (const float*)d_in[6];
    const float* W_kj  = (const float*)d_in[7];
    const float* b_kj  = (const float*)d_in[8];
    const float* W_ji  = (const float*)d_in[9];
    const float* b_ji  = (const float*)d_in[10];
    const float* W_bil = (const float*)d_in[11];
    const float* r1_w1 = (const float*)d_in[12];
    const float* r1_b1 = (const float*)d_in[13];
    const float* r1_w2 = (const float*)d_in[14];
    const float* r1_b2 = (const float*)d_in[15];
    const float* r2_w1 = (const float*)d_in[16];
    const float* r2_b1 = (const float*)d_in[17];
    const float* r2_w2 = (const float*)d_in[18];
    const float* r2_b2 = (const float*)d_in[19];
    const float* W_out = (const float*)d_in[20];
    const float* b_out = (const float*)d_in[21];
    float* out = (float*)d_out;

    float *rbfp, *g, *p, *U, *m1, *tb, *m2, *m3;
    cudaGetSymbolAddress((void**)&rbfp, g_rbfp);
    cudaGetSymbolAddress((void**)&g,    g_g);
    cudaGetSymbolAddress((void**)&p,    g_p);
    cudaGetSymbolAddress((void**)&U,    g_U);
    cudaGetSymbolAddress((void**)&m1,   g_m1);
    cudaGetSymbolAddress((void**)&tb,   g_tb);
    cudaGetSymbolAddress((void**)&m2,   g_m2);
    cudaGetSymbolAddress((void**)&m3,   g_m3);

    const int* kj = tri;        // triplet_index[0]
    const int* ji = tri + TT;   // triplet_index[1]

    dim3 blk(256);
    dim3 grd(EE / 128, 1);

    // Per-edge precomputations
    rbfproj_kernel<<<(EE * HH) / 256, 256>>>(rbf, W_rbf, rbfp);
    sbfproj_kernel<<<TT / 32, 256>>>(sbf, W_sbf, p);

    // m1 = x_ji = silu(m @ W_ji + b_ji)
    gemm_k<1, 0><<<grd, blk>>>(m, W_ji, HH, b_ji, nullptr, m1, HH);
    // g = silu(m @ W_kj + b_kj) * rbfproj
    gemm_k<2, 0><<<grd, blk>>>(m, W_kj, HH, b_kj, rbfp, g, HH);
    // U = g @ W_bil_flat  [E, 1024]
    gemm_k<0, 0><<<dim3(EE / 128, NBIL), blk>>>(g, W_bil, NBIL * HH, nullptr, nullptr, U, NBIL * HH);

    // Triplet pass: m1 += segment_sum(msg, ji)
    msg_kernel<<<TT / 8, 256>>>(U, kj, ji, p, m1);

    // Residual block 1
    gemm_k<1, 1><<<grd, blk>>>(m1, r1_w1, HH, r1_b1, nullptr, tb, HH);
    gemm_k<3, 0><<<grd, blk>>>(tb, r1_w2, HH, r1_b2, m1, m2, HH);
    // Residual block 2
    gemm_k<1, 1><<<grd, blk>>>(m2, r2_w1, HH, r2_b1, nullptr, tb, HH);
    gemm_k<3, 0><<<grd, blk>>>(tb, r2_w2, HH, r2_b2, m2, m3, HH);
    // out = m + silu(m3 @ W_out + b_out)
    gemm_k<4, 0><<<grd, blk>>>(m3, W_out, HH, b_out, m, out, HH);
}

// round 3
// speedup vs baseline: 1.3857x; 1.3857x over previous
#include <cuda_runtime.h>
#include <cstdint>
#include <cstddef>

// Problem constants
#define EE 131072
#define TT 1048576
#define HH 128
#define NRBF 6
#define NSBF 42
#define NBIL 8

// ---------------------------------------------------------------------------
// Scratch (device globals; no runtime allocation allowed)
// ---------------------------------------------------------------------------
__device__ float g_rbfp[(size_t)EE * HH];          //  64 MB
__device__ float g_g   [(size_t)EE * HH];          //  64 MB
__device__ float g_p   [(size_t)TT * NBIL];        //  32 MB
__device__ float g_U   [(size_t)EE * NBIL * HH];   // 512 MB
__device__ float g_m1  [(size_t)EE * HH];          //  64 MB
__device__ float g_tb  [(size_t)EE * HH];          //  64 MB
__device__ float g_m2  [(size_t)EE * HH];          //  64 MB
__device__ float g_m3  [(size_t)EE * HH];          //  64 MB

__device__ __forceinline__ float silu_f(float x) {
    return x / (1.0f + __expf(-x));
}

__device__ __forceinline__ uint32_t f2tf32(float x) {
    uint32_t r;
    asm("cvt.rna.tf32.f32 %0, %1;" : "=r"(r) : "f"(x));
    return r;
}

__device__ __forceinline__ uint32_t smem_u32(const void* p) {
    return (uint32_t)__cvta_generic_to_shared(p);
}

// ---------------------------------------------------------------------------
// tf32 tensor-core GEMM: C = epilogue( op(A[M,128]) @ W[128, ldw] )
// Block tile 128x128, K=128 in 4 chunks of 32. 256 threads = 8 warps (2x4).
// Warp tile 64x32 -> 4x4 m16n8k8 tiles per k-step.
// MODE: 0 raw | 1 silu(x+b) | 2 silu(x+b)*extra | 3 x+b+extra | 4 extra+silu(x+b)
// PRE : 1 -> silu applied to A elements on load.
// SWAP: 1 -> blockIdx.y is the M tile, blockIdx.x the N tile (L2 A reuse for U).
// ---------------------------------------------------------------------------
template <int MODE, int PRE, int SWAP>
__global__ void __launch_bounds__(256)
gemm_tf32(const float* __restrict__ A,
          const float* __restrict__ W, int ldw,
          const float* __restrict__ bias,
          const float* __restrict__ extra,
          float* __restrict__ C, int ldc)
{
    __shared__ float As[128 * 36];   // stride 36: frag LDS conflict-free
    __shared__ float Bs[32 * 136];   // stride 136: frag LDS conflict-free

    const int m0 = (SWAP ? blockIdx.y : blockIdx.x) * 128;
    const int n0 = (SWAP ? blockIdx.x : blockIdx.y) * 128;

    const int tid  = threadIdx.x;
    const int lane = tid & 31;
    const int wid  = tid >> 5;
    const int wm   = wid >> 2;      // 0..1
    const int wn   = wid & 3;       // 0..3
    const int g    = lane >> 2;     // groupID 0..7
    const int tg   = lane & 3;      // threadID_in_group 0..3

    float acc[4][4][4];
#pragma unroll
    for (int i = 0; i < 4; ++i)
#pragma unroll
        for (int j = 0; j < 4; ++j)
#pragma unroll
            for (int k = 0; k < 4; ++k) acc[i][j][k] = 0.0f;

    for (int cc = 0; cc < 4; ++cc) {
        const int k0 = cc * 32;

        // ---- stage A chunk [128 x 32] ----
        if (PRE) {
#pragma unroll
            for (int i = 0; i < 4; ++i) {
                int L = tid + i * 256;
                int r = L >> 3, cq = L & 7;
                float4 v = *reinterpret_cast<const float4*>(
                    A + (size_t)(m0 + r) * HH + k0 + cq * 4);
                v.x = silu_f(v.x); v.y = silu_f(v.y);
                v.z = silu_f(v.z); v.w = silu_f(v.w);
                *reinterpret_cast<float4*>(&As[r * 36 + cq * 4]) = v;
            }
        } else {
#pragma unroll
            for (int i = 0; i < 4; ++i) {
                int L = tid + i * 256;
                int r = L >> 3, cq = L & 7;
                uint32_t dst = smem_u32(&As[r * 36 + cq * 4]);
                const float* src = A + (size_t)(m0 + r) * HH + k0 + cq * 4;
                asm volatile("cp.async.ca.shared.global [%0], [%1], 16;\n"
                             :: "r"(dst), "l"(src));
            }
        }
        // ---- stage B chunk [32 x 128] ----
#pragma unroll
        for (int i = 0; i < 4; ++i) {
            int L = tid + i * 256;
            int kr = L >> 5, nq = L & 31;
            uint32_t dst = smem_u32(&Bs[kr * 136 + nq * 4]);
            const float* src = W + (size_t)(k0 + kr) * ldw + n0 + nq * 4;
            asm volatile("cp.async.ca.shared.global [%0], [%1], 16;\n"
                         :: "r"(dst), "l"(src));
        }
        asm volatile("cp.async.commit_group;\n");
        asm volatile("cp.async.wait_group 0;\n");
        __syncthreads();

        // ---- compute 4 k-steps of 8 ----
#pragma unroll
        for (int ks = 0; ks < 4; ++ks) {
            uint32_t af[4][4], bf[4][2];
#pragma unroll
            for (int mi = 0; mi < 4; ++mi) {
                int r = wm * 64 + mi * 16 + g;
                const float* ap = &As[r * 36 + ks * 8 + tg];
                af[mi][0] = f2tf32(ap[0]);
                af[mi][1] = f2tf32(ap[8 * 36]);
                af[mi][2] = f2tf32(ap[4]);
                af[mi][3] = f2tf32(ap[8 * 36 + 4]);
            }
#pragma unroll
            for (int ni = 0; ni < 4; ++ni) {
                int c = wn * 32 + ni * 8 + g;
                const float* bp = &Bs[(ks * 8 + tg) * 136 + c];
                bf[ni][0] = f2tf32(bp[0]);
                bf[ni][1] = f2tf32(bp[4 * 136]);
            }
#pragma unroll
            for (int mi = 0; mi < 4; ++mi)
#pragma unroll
                for (int ni = 0; ni < 4; ++ni)
                    asm volatile(
                        "mma.sync.aligned.m16n8k8.row.col.f32.tf32.tf32.f32 "
                        "{%0,%1,%2,%3}, {%4,%5,%6,%7}, {%8,%9}, {%0,%1,%2,%3};"
                        : "+f"(acc[mi][ni][0]), "+f"(acc[mi][ni][1]),
                          "+f"(acc[mi][ni][2]), "+f"(acc[mi][ni][3])
                        : "r"(af[mi][0]), "r"(af[mi][1]),
                          "r"(af[mi][2]), "r"(af[mi][3]),
                          "r"(bf[ni][0]), "r"(bf[ni][1]));
        }
        __syncthreads();
    }

    // ---- epilogue ----
#pragma unroll
    for (int mi = 0; mi < 4; ++mi) {
#pragma unroll
        for (int half = 0; half < 2; ++half) {
            size_t row = (size_t)m0 + wm * 64 + mi * 16 + g + half * 8;
#pragma unroll
            for (int ni = 0; ni < 4; ++ni) {
                int col = n0 + wn * 32 + ni * 8 + tg * 2;
                float2 v = half == 0
                    ? make_float2(acc[mi][ni][0], acc[mi][ni][1])
                    : make_float2(acc[mi][ni][2], acc[mi][ni][3]);
                if (MODE != 0) {
                    float2 bb = *reinterpret_cast<const float2*>(bias + col);
                    v.x += bb.x; v.y += bb.y;
                }
                if (MODE == 1 || MODE == 2 || MODE == 4) {
                    v.x = silu_f(v.x); v.y = silu_f(v.y);
                }
                if (MODE == 2) {
                    float2 e = *reinterpret_cast<const float2*>(extra + row * HH + col);
                    v.x *= e.x; v.y *= e.y;
                }
                if (MODE == 3 || MODE == 4) {
                    float2 e = *reinterpret_cast<const float2*>(extra + row * HH + col);
                    v.x += e.x; v.y += e.y;
                }
                *reinterpret_cast<float2*>(C + row * (size_t)ldc + col) = v;
            }
        }
    }
}

// ---------------------------------------------------------------------------
// rbfproj[e, c] = sum_r rbf[e, r] * W_rbf[r, c]
// ---------------------------------------------------------------------------
__global__ void __launch_bounds__(256)
rbfproj_kernel(const float* __restrict__ rbf,
               const float* __restrict__ Wrbf,
               float* __restrict__ out)
{
    int idx = blockIdx.x * 256 + threadIdx.x;
    int e = idx >> 7;
    int c = idx & 127;
    const float* r = rbf + (size_t)e * NRBF;
    float acc = 0.0f;
#pragma unroll
    for (int k = 0; k < NRBF; ++k)
        acc += r[k] * Wrbf[k * HH + c];
    out[idx] = acc;
}

// ---------------------------------------------------------------------------
// p[t, b] = sum_k sbf[t, k] * W_sbf[k, b]
// ---------------------------------------------------------------------------
__global__ void __launch_bounds__(256)
sbfproj_kernel(const float* __restrict__ sbf,
               const float* __restrict__ Wsbf,
               float* __restrict__ p)
{
    __shared__ float s_sbf[32][NSBF];
    __shared__ float s_w[NSBF][NBIL];

    int t0  = blockIdx.x * 32;
    int tid = threadIdx.x;

    for (int i = tid; i < NSBF * NBIL; i += 256)
        s_w[i / NBIL][i % NBIL] = Wsbf[i];
    for (int i = tid; i < 32 * NSBF; i += 256) {
        int tl = i / NSBF, c = i % NSBF;
        s_sbf[tl][c] = sbf[(size_t)(t0 + tl) * NSBF + c];
    }
    __syncthreads();

    int tl = tid >> 3;
    int b  = tid & 7;
    float acc = 0.0f;
#pragma unroll
    for (int k = 0; k < NSBF; ++k)
        acc += s_sbf[tl][k] * s_w[k][b];
    p[(size_t)(t0 + tl) * NBIL + b] = acc;
}

// ---------------------------------------------------------------------------
// Triplet message + scatter: one warp per triplet.
// ---------------------------------------------------------------------------
__global__ void __launch_bounds__(256)
msg_kernel(const float* __restrict__ U,
           const int* __restrict__ kj,
           const int* __restrict__ ji,
           const float* __restrict__ p,
           float* __restrict__ out)
{
    int warp = (blockIdx.x * 256 + threadIdx.x) >> 5;
    int lane = threadIdx.x & 31;

    int ekj = kj[warp];
    int eji = ji[warp];

    const float4* u = reinterpret_cast<const float4*>(U + (size_t)ekj * (NBIL * HH)) + lane;
    const float* pp = p + (size_t)warp * NBIL;

    float pb[NBIL];
#pragma unroll
    for (int b = 0; b < NBIL; ++b) pb[b] = pp[b];

    float4 acc = make_float4(0.f, 0.f, 0.f, 0.f);
#pragma unroll
    for (int b = 0; b < NBIL; ++b) {
        float4 uv = u[b * 32];
        acc.x += pb[b] * uv.x;
        acc.y += pb[b] * uv.y;
        acc.z += pb[b] * uv.z;
        acc.w += pb[b] * uv.w;
    }

    float* o = out + (size_t)eji * HH + lane * 4;
    atomicAdd(o + 0, acc.x);
    atomicAdd(o + 1, acc.y);
    atomicAdd(o + 2, acc.z);
    atomicAdd(o + 3, acc.w);
}

// ---------------------------------------------------------------------------
// Launch
// ---------------------------------------------------------------------------
extern "C" void kernel_launch(void* const* d_in, const int* in_sizes, int n_in,
                              void* d_out, int out_size)
{
    const float* m     = (const float*)d_in[0];
    const float* rbf   = (const float*)d_in[1];
    const float* sbf   = (const float*)d_in[2];
    // d_in[3] = edge_index (unused by the reference)
    const int*   tri   = (const int*)d_in[4];
    const float* W_rbf = (const float*)d_in[5];
    const float* W_sbf = (const float*)d_in[6];
    const float* W_kj  = (const float*)d_in[7];
    const float* b_kj  = (const float*)d_in[8];
    const float* W_ji  = (const float*)d_in[9];
    const float* b_ji  = (const float*)d_in[10];
    const float* W_bil = (const float*)d_in[11];
    const float* r1_w1 = (const float*)d_in[12];
    const float* r1_b1 = (const float*)d_in[13];
    const float* r1_w2 = (const float*)d_in[14];
    const float* r1_b2 = (const float*)d_in[15];
    const float* r2_w1 = (const float*)d_in[16];
    const float* r2_b1 = (const float*)d_in[17];
    const float* r2_w2 = (const float*)d_in[18];
    const float* r2_b2 = (const float*)d_in[19];
    const float* W_out = (const float*)d_in[20];
    const float* b_out = (const float*)d_in[21];
    float* out = (float*)d_out;

    float *rbfp, *g, *p, *U, *m1, *tb, *m2, *m3;
    cudaGetSymbolAddress((void**)&rbfp, g_rbfp);
    cudaGetSymbolAddress((void**)&g,    g_g);
    cudaGetSymbolAddress((void**)&p,    g_p);
    cudaGetSymbolAddress((void**)&U,    g_U);
    cudaGetSymbolAddress((void**)&m1,   g_m1);
    cudaGetSymbolAddress((void**)&tb,   g_tb);
    cudaGetSymbolAddress((void**)&m2,   g_m2);
    cudaGetSymbolAddress((void**)&m3,   g_m3);

    const int* kj = tri;        // triplet_index[0]
    const int* ji = tri + TT;   // triplet_index[1]

    dim3 blk(256);
    dim3 grd(EE / 128, 1);

    // Per-edge precomputations
    rbfproj_kernel<<<(EE * HH) / 256, 256>>>(rbf, W_rbf, rbfp);
    sbfproj_kernel<<<TT / 32, 256>>>(sbf, W_sbf, p);

    // m1 = x_ji = silu(m @ W_ji + b_ji)
    gemm_tf32<1, 0, 0><<<grd, blk>>>(m, W_ji, HH, b_ji, nullptr, m1, HH);
    // g = silu(m @ W_kj + b_kj) * rbfproj
    gemm_tf32<2, 0, 0><<<grd, blk>>>(m, W_kj, HH, b_kj, rbfp, g, HH);
    // U = g @ W_bil_flat  [E, 1024]; SWAP=1 -> 8 consecutive CTAs share one A tile
    gemm_tf32<0, 0, 1><<<dim3(NBIL, EE / 128), blk>>>(g, W_bil, NBIL * HH,
                                                      nullptr, nullptr, U, NBIL * HH);

    // Triplet pass: m1 += segment_sum(msg, ji)
    msg_kernel<<<TT / 8, 256>>>(U, kj, ji, p, m1);

    // Residual block 1
    gemm_tf32<1, 1, 0><<<grd, blk>>>(m1, r1_w1, HH, r1_b1, nullptr, tb, HH);
    gemm_tf32<3, 0, 0><<<grd, blk>>>(tb, r1_w2, HH, r1_b2, m1, m2, HH);
    // Residual block 2
    gemm_tf32<1, 1, 0><<<grd, blk>>>(m2, r2_w1, HH, r2_b1, nullptr, tb, HH);
    gemm_tf32<3, 0, 0><<<grd, blk>>>(tb, r2_w2, HH, r2_b2, m2, m3, HH);
    // out = m + silu(m3 @ W_out + b_out)
    gemm_tf32<4, 0, 0><<<grd, blk>>>(m3, W_out, HH, b_out, m, out, HH);
}